// round 3
// baseline (speedup 1.0000x reference)
#include <cuda_runtime.h>

// x: (B=8, C=512, T=16, W=28, H=28) fp32, contiguous.
// Per (b,c) slice = 16*28*28 = 12544 floats.
// Fused: one pass computes 4x4x4 = 64 window maxes m4[tt][wi][hi]
// (window 4x7x7, stride 4x7x7), from which all three branch outputs derive:
//   out[0]      = max over all 64                      (n=1)
//   out[1+tt2]  = mean_{wi2,hi2} max over 2x2x2 block  (n=2)
//   out[3+tt]   = mean_{wi,hi}   m4[tt][wi][hi]        (n=4)
// (In every branch Ty==n and L==1, so the temporal multiply is identity.)

#define SLICE   12544   // 16*28*28
#define TCHUNK  3136    // 4*28*28 (one temporal window-depth)
#define NBC     4096    // 8*512

__global__ __launch_bounds__(256, 8)
void tmp3d_fused_kernel(const float* __restrict__ x, float* __restrict__ out) {
    __shared__ float tile[2 * TCHUNK];   // two t-chunks: 25.1 KB
    __shared__ float m4s[64];            // [tc*16 + wi*4 + hi]

    const int bc   = blockIdx.x;        // 0..4095  == b*512 + c
    const int tid  = threadIdx.x;
    const int warp = tid >> 5;          // 0..7
    const int lane = tid & 31;
    const int slice_base = bc * SLICE;  // max 4095*12544 < 2^31, int ok

    constexpr int NVEC = 2 * TCHUNK / 4;          // 1568 float4 per round
    constexpr int NIT  = (NVEC + 255) / 256;      // 7 iterations

    #pragma unroll 1
    for (int pair = 0; pair < 2; pair++) {        // chunks {0,1} then {2,3}
        // ---- coalesced load of two t-chunks into smem ----
        const float4* src = reinterpret_cast<const float4*>(
            x + slice_base + pair * 2 * TCHUNK);
        float4* dst = reinterpret_cast<float4*>(tile);
        #pragma unroll
        for (int i = 0; i < NIT; i++) {
            const int idx = tid + i * 256;
            if (idx < NVEC) dst[idx] = src[idx];
        }
        __syncthreads();

        // ---- 32 spatial windows (2 chunks x 16), 4 per warp ----
        #pragma unroll
        for (int k = 0; k < 4; k++) {
            const int widx = warp * 4 + k;      // 0..31
            const int half = widx >> 4;         // which chunk in the pair
            const int sp   = widx & 15;         // spatial window 0..15
            const int wi = sp >> 2;
            const int hi = sp & 3;
            const float* base = tile + half * TCHUNK + wi * 7 * 28 + hi * 7;
            float m = -3.402823466e+38f;
            #pragma unroll
            for (int t = 0; t < 4; t++) {
                const float* bt = base + t * 784;
                for (int e = lane; e < 49; e += 32) {
                    const int w = e / 7;
                    const int h = e - w * 7;
                    m = fmaxf(m, bt[w * 28 + h]);
                }
            }
            #pragma unroll
            for (int off = 16; off > 0; off >>= 1)
                m = fmaxf(m, __shfl_xor_sync(0xffffffffu, m, off));
            if (lane == 0)
                m4s[(pair * 2 + half) * 16 + sp] = m;
        }
        __syncthreads();   // m4s written; tile safe to overwrite next pair
    }

    // ---- tiny finishing tree: 7 outputs, one per thread 0..6 ----
    if (tid < 7) {
        float r;
        if (tid == 0) {
            // n=1: global max
            float m = m4s[0];
            #pragma unroll
            for (int i = 1; i < 64; i++) m = fmaxf(m, m4s[i]);
            r = m;
        } else if (tid < 3) {
            // n=2: mean over 2x2 spatial of (max over 2x2x2 m4 block)
            const int tt2 = tid - 1;
            float s = 0.0f;
            #pragma unroll
            for (int wi2 = 0; wi2 < 2; wi2++) {
                #pragma unroll
                for (int hi2 = 0; hi2 < 2; hi2++) {
                    float m = -3.402823466e+38f;
                    #pragma unroll
                    for (int dt = 0; dt < 2; dt++)
                        #pragma unroll
                        for (int dw = 0; dw < 2; dw++)
                            #pragma unroll
                            for (int dh = 0; dh < 2; dh++)
                                m = fmaxf(m, m4s[(2*tt2 + dt) * 16 +
                                                 (2*wi2 + dw) * 4 + (2*hi2 + dh)]);
                    s += m;
                }
            }
            r = s * 0.25f;
        } else {
            // n=4: mean over 4x4 spatial
            const int tt = tid - 3;
            float s = 0.0f;
            #pragma unroll
            for (int i = 0; i < 16; i++) s += m4s[tt * 16 + i];
            r = s * (1.0f / 16.0f);
        }
        out[bc * 7 + tid] = r;
    }
}

extern "C" void kernel_launch(void* const* d_in, const int* in_sizes, int n_in,
                              void* d_out, int out_size) {
    const float* x = (const float*)d_in[0];
    float* out = (float*)d_out;
    tmp3d_fused_kernel<<<NBC, 256>>>(x, out);
}

// round 6
// speedup vs baseline: 1.3351x; 1.3351x over previous
#include <cuda_runtime.h>

// x: (B=8, C=512, T=16, W=28, H=28) fp32, contiguous.
// Fused decomposition onto 4x4x4 = 64 window maxes m4[tt][wi][hi]
// (window 4x7x7, stride 4x7x7); all three branches derive from m4
// (temporal multiply is identity since L=1 in every branch):
//   out[0]      = max over all 64                      (n=1)
//   out[1+tt2]  = mean_{wi2,hi2} max over 2x2x2 block  (n=2)
//   out[3+tt]   = mean_{wi,hi}   m4[tt][wi][hi]        (n=4)

#define SLICE   12544   // 16*28*28
#define TCHUNK  3136    // 4*28*28
#define NBC     4096    // 8*512
#define ROWLEN  28      // floats per (t,w) row
#define NROWS   224     // rows per staged pair: 2 chunks * 4t * 28w

__global__ __launch_bounds__(256, 6)
void tmp3d_fused_kernel(const float* __restrict__ x, float* __restrict__ out) {
    __shared__ float tile[2 * TCHUNK];   // 224 rows x 28 floats = 25.1 KB
    __shared__ float pm[4][NROWS];       // per-row partial maxes, [hi][row]
    __shared__ float m4s[64];            // [tt*16 + wi*4 + hi]

    const int bc   = blockIdx.x;
    const int tid  = threadIdx.x;
    const int slice_base = bc * SLICE;

    constexpr int NVEC = 2 * TCHUNK / 4;      // 1568 float4 per pair
    constexpr int NIT  = (NVEC + 255) / 256;  // 7

    #pragma unroll 1
    for (int pair = 0; pair < 2; pair++) {
        // ---- stage two t-chunks, coalesced float4 ----
        const float4* src = reinterpret_cast<const float4*>(
            x + slice_base + pair * 2 * TCHUNK);
        float4* dst = reinterpret_cast<float4*>(tile);
        #pragma unroll
        for (int i = 0; i < NIT; i++) {
            const int idx = tid + i * 256;
            if (idx < NVEC) dst[idx] = src[idx];
        }
        __syncthreads();

        // ---- row phase: thread r handles one 28-float row ----
        // 7 conflict-free LDS.128, fold into 4 per-hi maxes.
        if (tid < NROWS) {
            const float4* rp = reinterpret_cast<const float4*>(tile + tid * ROWLEN);
            float4 v0 = rp[0], v1 = rp[1], v2 = rp[2], v3 = rp[3];
            float4 v4 = rp[4], v5 = rp[5], v6 = rp[6];
            // hi0: h 0..6
            float m0 = fmaxf(fmaxf(fmaxf(v0.x, v0.y), fmaxf(v0.z, v0.w)),
                             fmaxf(fmaxf(v1.x, v1.y), v1.z));
            // hi1: h 7..13
            float m1 = fmaxf(fmaxf(fmaxf(v1.w, v2.x), fmaxf(v2.y, v2.z)),
                             fmaxf(fmaxf(v2.w, v3.x), v3.y));
            // hi2: h 14..20
            float m2 = fmaxf(fmaxf(fmaxf(v3.z, v3.w), fmaxf(v4.x, v4.y)),
                             fmaxf(fmaxf(v4.z, v4.w), v5.x));
            // hi3: h 21..27
            float m3 = fmaxf(fmaxf(fmaxf(v5.y, v5.z), fmaxf(v5.w, v6.x)),
                             fmaxf(fmaxf(v6.y, v6.z), v6.w));
            pm[0][tid] = m0;   // conflict-free: consecutive tid -> consecutive banks
            pm[1][tid] = m1;
            pm[2][tid] = m2;
            pm[3][tid] = m3;
        }
        __syncthreads();

        // ---- window phase: warp 0 reduces 28 pm entries per window ----
        if (tid < 32) {
            const int c  = tid >> 4;       // chunk within pair
            const int sp = tid & 15;
            const int wi = sp >> 2;
            const int hi = sp & 3;
            const float* p = &pm[hi][c * 112 + wi * 7];
            float m = -3.402823466e+38f;
            #pragma unroll
            for (int t = 0; t < 4; t++) {
                #pragma unroll
                for (int dw = 0; dw < 7; dw++)
                    m = fmaxf(m, p[t * 28 + dw]);
            }
            m4s[(pair * 2 + c) * 16 + sp] = m;
        }
        // no sync needed here: next staging touches only tile; next row phase
        // (which overwrites pm) is behind the staging __syncthreads.
    }
    __syncthreads();   // m4s complete

    // ---- finishing tree: 7 outputs ----
    if (tid < 7) {
        float r;
        if (tid == 0) {
            float m = m4s[0];
            #pragma unroll
            for (int i = 1; i < 64; i++) m = fmaxf(m, m4s[i]);
            r = m;
        } else if (tid < 3) {
            const int tt2 = tid - 1;
            float s = 0.0f;
            #pragma unroll
            for (int wi2 = 0; wi2 < 2; wi2++) {
                #pragma unroll
                for (int hi2 = 0; hi2 < 2; hi2++) {
                    float m = -3.402823466e+38f;
                    #pragma unroll
                    for (int dt = 0; dt < 2; dt++)
                        #pragma unroll
                        for (int dw = 0; dw < 2; dw++)
                            #pragma unroll
                            for (int dh = 0; dh < 2; dh++)
                                m = fmaxf(m, m4s[(2*tt2 + dt) * 16 +
                                                 (2*wi2 + dw) * 4 + (2*hi2 + dh)]);
                    s += m;
                }
            }
            r = s * 0.25f;
        } else {
            const int tt = tid - 3;
            float s = 0.0f;
            #pragma unroll
            for (int i = 0; i < 16; i++) s += m4s[tt * 16 + i];
            r = s * (1.0f / 16.0f);
        }
        out[bc * 7 + tid] = r;
    }
}

extern "C" void kernel_launch(void* const* d_in, const int* in_sizes, int n_in,
                              void* d_out, int out_size) {
    const float* x = (const float*)d_in[0];
    float* out = (float*)d_out;
    tmp3d_fused_kernel<<<NBC, 256>>>(x, out);
}

// round 7
// speedup vs baseline: 1.7878x; 1.3390x over previous
#include <cuda_runtime.h>
#include <cstdint>

// x: (B=8, C=512, T=16, W=28, H=28) fp32, contiguous.
// All three branches decompose onto 4x4x4 = 64 window maxes m4[tt][wi][hi]
// (window 4x7x7, stride 4x7x7); temporal multiply is identity (L=1):
//   out[0]      = max over all 64                      (n=1)
//   out[1+tt2]  = mean_{wi2,hi2} max over 2x2x2 block  (n=2)
//   out[3+tt]   = mean_{wi,hi}   m4[tt][wi][hi]        (n=4)

#define SLICE   12544   // 16*28*28
#define TCHUNK  3136    // 4*28*28 (one temporal window-depth)
#define NBC     4096    // 8*512

__device__ __forceinline__ void cp_async16(uint32_t dst_smem, const void* src) {
    asm volatile("cp.async.cg.shared.global [%0], [%1], 16;\n"
                 :: "r"(dst_smem), "l"(src));
}
__device__ __forceinline__ void cp_commit() {
    asm volatile("cp.async.commit_group;\n" ::: "memory");
}
template <int N>
__device__ __forceinline__ void cp_wait() {
    asm volatile("cp.async.wait_group %0;\n" :: "n"(N) : "memory");
}

__global__ __launch_bounds__(256, 8)
void tmp3d_fused_kernel(const float* __restrict__ x, float* __restrict__ out) {
    __shared__ float tile[2][TCHUNK];   // double buffer: 2 x 12.5 KB
    __shared__ float pm[4][112];        // per-half-row partial maxes [hi][t'*28+w]
    __shared__ float m4s[64];           // [tt*16 + wi*4 + hi]

    const int bc  = blockIdx.x;
    const int tid = threadIdx.x;
    const float* slice = x + bc * SLICE;

    const uint32_t tile_s = (uint32_t)__cvta_generic_to_shared(&tile[0][0]);

    // ---- prefetch helper: chunk c -> buffer b (784 x 16B LDGSTS) ----
    auto prefetch = [&](int c, int b) {
        const float* src = slice + c * TCHUNK;
        const uint32_t dst = tile_s + b * (TCHUNK * 4);
        cp_async16(dst + tid * 16, src + tid * 4);
        cp_async16(dst + (tid + 256) * 16, src + (tid + 256) * 4);
        cp_async16(dst + (tid + 512) * 16, src + (tid + 512) * 4);
        if (tid < 784 - 768)
            cp_async16(dst + (tid + 768) * 16, src + (tid + 768) * 4);
        cp_commit();
    };

    prefetch(0, 0);
    prefetch(1, 1);

    #pragma unroll
    for (int tc = 0; tc < 4; tc++) {
        if (tc == 3) cp_wait<0>(); else cp_wait<1>();   // buf[tc&1] landed
        __syncthreads();

        const float* buf = tile[tc & 1];

        // ---- row phase: 224 threads, one half-row (14 floats) each ----
        // half 0 -> hi{0,1}, half 1 -> hi{2,3}. Conflict-free LDS.128.
        if (tid < 224) {
            const int half = tid / 112;          // 0 or 1
            const int r    = tid - half * 112;   // row (t'*28 + w), t' in 0..3
            const float4* rp = reinterpret_cast<const float4*>(buf + r * 28 + half * 12);
            float4 v0 = rp[0], v1 = rp[1], v2 = rp[2], v3 = rp[3];
            float ma, mb;
            if (half == 0) {
                // ma = max h0..6, mb = max h7..13  (floats 0..15 of row)
                ma = fmaxf(fmaxf(fmaxf(v0.x, v0.y), fmaxf(v0.z, v0.w)),
                           fmaxf(fmaxf(v1.x, v1.y), v1.z));
                mb = fmaxf(fmaxf(fmaxf(v1.w, v2.x), fmaxf(v2.y, v2.z)),
                           fmaxf(fmaxf(v2.w, v3.x), v3.y));
            } else {
                // floats 12..27 of row: ma = max h14..20, mb = max h21..27
                ma = fmaxf(fmaxf(fmaxf(v0.z, v0.w), fmaxf(v1.x, v1.y)),
                           fmaxf(fmaxf(v1.z, v1.w), v2.x));
                mb = fmaxf(fmaxf(fmaxf(v2.y, v2.z), fmaxf(v2.w, v3.x)),
                           fmaxf(fmaxf(v3.y, v3.z), v3.w));
            }
            pm[2 * half + 0][r] = ma;
            pm[2 * half + 1][r] = mb;
        }
        __syncthreads();   // pm ready AND all tile[tc&1] reads done

        // ---- prefetch chunk tc+2 into the buffer just freed ----
        if (tc < 2) prefetch(tc + 2, tc & 1);

        // ---- window phase: 16 windows of this chunk, threads 0..15 ----
        if (tid < 16) {
            const int wi = tid >> 2;
            const int hi = tid & 3;
            const float* p = &pm[hi][wi * 7];
            float m = -3.402823466e+38f;
            #pragma unroll
            for (int t = 0; t < 4; t++) {
                #pragma unroll
                for (int dw = 0; dw < 7; dw++)
                    m = fmaxf(m, p[t * 28 + dw]);
            }
            m4s[tc * 16 + wi * 4 + hi] = m;
        }
        // next iteration's top syncthreads orders: window reads of pm
        // before next row phase overwrites pm.
    }
    __syncthreads();   // m4s complete

    // ---- finishing tree: 7 outputs ----
    if (tid < 7) {
        float r;
        if (tid == 0) {
            float m = m4s[0];
            #pragma unroll
            for (int i = 1; i < 64; i++) m = fmaxf(m, m4s[i]);
            r = m;
        } else if (tid < 3) {
            const int tt2 = tid - 1;
            float s = 0.0f;
            #pragma unroll
            for (int wi2 = 0; wi2 < 2; wi2++) {
                #pragma unroll
                for (int hi2 = 0; hi2 < 2; hi2++) {
                    float m = -3.402823466e+38f;
                    #pragma unroll
                    for (int dt = 0; dt < 2; dt++)
                        #pragma unroll
                        for (int dw = 0; dw < 2; dw++)
                            #pragma unroll
                            for (int dh = 0; dh < 2; dh++)
                                m = fmaxf(m, m4s[(2*tt2 + dt) * 16 +
                                                 (2*wi2 + dw) * 4 + (2*hi2 + dh)]);
                    s += m;
                }
            }
            r = s * 0.25f;
        } else {
            const int tt = tid - 3;
            float s = 0.0f;
            #pragma unroll
            for (int i = 0; i < 16; i++) s += m4s[tt * 16 + i];
            r = s * (1.0f / 16.0f);
        }
        out[bc * 7 + tid] = r;
    }
}

extern "C" void kernel_launch(void* const* d_in, const int* in_sizes, int n_in,
                              void* d_out, int out_size) {
    const float* x = (const float*)d_in[0];
    float* out = (float*)d_out;
    tmp3d_fused_kernel<<<NBC, 256>>>(x, out);
}